// round 16
// baseline (speedup 1.0000x reference)
#include <cuda_runtime.h>
#include <cuda_bf16.h>

#define NN    6000
#define DEG   16
#define MM    17      // DEG+1
#define NT    16
#define MT    10
#define MTP   12      // padded row (floats)
#define NF    128
#define NKT   (NT*MT) // 160
#define REGc  0.1f
#define NWARPS 8
#define TPB_MAIN 256

#define GEMM_BLOCKS   ((NN + 31) / 32)          // 188 (32 rows per block)
#define SETUP_BLOCK   GEMM_BLOCKS               // 188
#define PREP_BLOCKS   (GEMM_BLOCKS + 1)         // 189

typedef unsigned long long u64;

// ---------------- device scratch (no cudaMalloc allowed) ----------------
__device__ float    g_f2n[NKT];
__device__ float    g_consts[3];     // cA = 2a/REG, cY = 4a/REG, cM = (1-a)/REG
__device__ float    g_D[NN * NKT];   // raw dot:  x[u] . F2[kt]

// ---------------- packed f32x2 helpers ----------------
__device__ __forceinline__ u64 pk2(float x, float y) {
    u64 r; asm("mov.b64 %0,{%1,%2};" : "=l"(r) : "f"(x), "f"(y)); return r;
}
__device__ __forceinline__ void up2(u64 v, float& x, float& y) {
    asm("mov.b64 {%0,%1},%2;" : "=f"(x), "=f"(y) : "l"(v));
}
__device__ __forceinline__ u64 add2(u64 a, u64 b) {
    u64 r; asm("add.rn.f32x2 %0,%1,%2;" : "=l"(r) : "l"(a), "l"(b)); return r;
}
__device__ __forceinline__ u64 mul2(u64 a, u64 b) {
    u64 r; asm("mul.rn.f32x2 %0,%1,%2;" : "=l"(r) : "l"(a), "l"(b)); return r;
}
__device__ __forceinline__ u64 fma2(u64 a, u64 b, u64 c) {
    u64 r; asm("fma.rn.f32x2 %0,%1,%2,%3;" : "=l"(r) : "l"(a), "l"(b), "l"(c)); return r;
}
__device__ __forceinline__ float hsum2(u64 v) {
    float x, y; up2(v, x, y); return x + y;
}

// packed f32x2 dot over 10 elements (both operands 16B-aligned smem rows)
__device__ __forceinline__ float dot10p(const float* __restrict__ a,
                                        const float* __restrict__ b) {
    const ulonglong2* A = (const ulonglong2*)a;
    const ulonglong2* B = (const ulonglong2*)b;
    ulonglong2 A0 = A[0], A1 = A[1];
    ulonglong2 B0 = B[0], B1 = B[1];
    u64 a2 = *(const u64*)(a + 8);
    u64 b2 = *(const u64*)(b + 8);
    u64 acc = mul2(A0.x, B0.x);
    acc = fma2(A0.y, B0.y, acc);
    acc = fma2(A1.x, B1.x, acc);
    acc = fma2(A1.y, B1.y, acc);
    acc = fma2(a2,   b2,   acc);
    return hsum2(acc);
}

// ---------------- fused prologue: setup | gemm ----------------
__global__ void __launch_bounds__(272, 3)
k_prep(const float* __restrict__ x, const float* __restrict__ F2,
       const float* __restrict__ alpha0) {
    __shared__ float sX[32][33];
    __shared__ float sF[32][161];

    const int tid = threadIdx.x;
    const int blk = blockIdx.x;

    if (blk < GEMM_BLOCKS) {
        const int tr = tid & 15;
        const int tc = (tid >> 4) & 15;
        const bool act = (tid < 256);
        const int r0 = blk * 32;

        float acc[2][10];
        #pragma unroll
        for (int i = 0; i < 2; i++)
            #pragma unroll
            for (int j = 0; j < 10; j++) acc[i][j] = 0.f;

        for (int k0 = 0; k0 < NF; k0 += 32) {
            __syncthreads();
            for (int idx = tid; idx < 256; idx += 272) {
                int rr = idx >> 3, c4 = idx & 7;
                int gr = r0 + rr;
                float4 v = (gr < NN) ? __ldg((const float4*)(x + (size_t)gr * NF + k0) + c4)
                                     : make_float4(0.f, 0.f, 0.f, 0.f);
                sX[c4*4+0][rr] = v.x; sX[c4*4+1][rr] = v.y;
                sX[c4*4+2][rr] = v.z; sX[c4*4+3][rr] = v.w;
            }
            for (int idx = tid; idx < 1280; idx += 272) {
                int cc = idx >> 3, c4 = idx & 7;
                float4 v = __ldg((const float4*)(F2 + (size_t)cc * NF + k0) + c4);
                sF[c4*4+0][cc] = v.x; sF[c4*4+1][cc] = v.y;
                sF[c4*4+2][cc] = v.z; sF[c4*4+3][cc] = v.w;
            }
            __syncthreads();

            if (act) {
                #pragma unroll 4
                for (int kk = 0; kk < 32; kk++) {
                    float b[10];
                    #pragma unroll
                    for (int j = 0; j < 10; j++) b[j] = sF[kk][tc*10 + j];
                    #pragma unroll
                    for (int i = 0; i < 2; i++) {
                        float a = sX[kk][tr + 16*i];
                        #pragma unroll
                        for (int j = 0; j < 10; j++) acc[i][j] = fmaf(a, b[j], acc[i][j]);
                    }
                }
            }
        }

        if (act) {
            #pragma unroll
            for (int i = 0; i < 2; i++) {
                int r = r0 + tr + 16*i;
                if (r < NN) {
                    float* drow = g_D + (size_t)r * NKT + tc*10;
                    #pragma unroll
                    for (int j = 0; j < 10; j++) drow[j] = acc[i][j];
                }
            }
        }
    } else {
        if (tid == 0) {
            float a0 = alpha0[0];
            float alpha = 1.0f / (1.0f + __expf(-a0));
            g_consts[0] = 2.0f * alpha / REGc;
            g_consts[1] = 4.0f * alpha / REGc;
            g_consts[2] = (1.0f - alpha) / REGc;
        }
        for (int idx = tid; idx < NKT; idx += 272) {
            const float* row = F2 + (size_t)idx * NF;
            float s = 0.f;
            #pragma unroll 8
            for (int f = 0; f < NF; f++) { float v = row[f]; s += v * v; }
            g_f2n[idx] = s;
        }
    }
}

// ---------------- main: warp-synchronous, fused adjacency ----------------
// block = 1 node, 8 warps; warp = 2 templates x 16 rows (+ distributed row 0)
__global__ void __launch_bounds__(TPB_MAIN, 3)
k_main(const float* __restrict__ C2g, const int* __restrict__ dst,
       float* __restrict__ out) {
    __shared__ __align__(16) float sT [NT][MM][MTP];
    __shared__ __align__(16) float sW [NT][MM][MTP];
    __shared__ __align__(16) float sC2[NT][MT][MTP];
    __shared__ __align__(16) float sq [NT][MTP];
    __shared__ __align__(16) float sU [NT][MTP];
    __shared__ __align__(16) float sRS [NT][MTP];
    __shared__ __align__(16) float sRS2[NT][MTP];
    __shared__ int sList[NWARPS][32];
    __shared__ int sLn[NWARPS];
    __shared__ int      sNbr[MM];
    __shared__ unsigned sBB [MM];
    __shared__ unsigned sMsk[MM];

    const int tid = threadIdx.x;
    const int n   = blockIdx.x;
    const int w   = tid >> 5;
    const int l   = tid & 31;
    const int g   = l >> 4;            // template within warp
    const int j   = l & 15;            // 0..15
    const int kk  = w * 2 + g;         // global template 0..15
    const int r   = j + 1;             // own row 1..16
    const bool sl = (j < MT);          // s-lane (owns output column j)

    const float cA = g_consts[0];
    const float cY = g_consts[1];
    const float cM = g_consts[2];

    // ---- adjacency prologue: neighbor list ----
    if (tid < MM)
        sNbr[tid] = (tid == 0) ? n : __ldg(dst + (size_t)n * DEG + tid - 1);
    __syncthreads();

    // warp-local C2 load (2 templates)
    for (int idx = l; idx < 2 * MT * MTP; idx += 32) {
        int kkk = w*2 + idx / (MT*MTP);
        int rr  = idx % (MT*MTP);
        int s2  = rr / MTP, t2 = rr % MTP;
        sC2[kkk][s2][t2] = (t2 < MT) ? C2g[(kkk*MT + s2)*MT + t2] : 0.f;
    }

    // ---- B bits: 17 rows x 8 lanes; unpredicated shuffles ----
    {
        int i2 = tid >> 3;                 // 0..31
        int e2 = tid & 7;
        int ic = (i2 < MM) ? i2 : 0;       // clamp for safe dummy work
        int u2 = sNbr[ic];
        int dua = __ldg(dst + (size_t)u2 * DEG + e2);
        int dub = __ldg(dst + (size_t)u2 * DEG + e2 + 8);
        unsigned bits = 0;
        #pragma unroll
        for (int jj = 0; jj < MM; jj++) {
            int v = sNbr[jj];
            bits |= (unsigned)((dua == v) | (dub == v)) << jj;
        }
        bits |= __shfl_xor_sync(0xffffffffu, bits, 1, 8);
        bits |= __shfl_xor_sync(0xffffffffu, bits, 2, 8);
        bits |= __shfl_xor_sync(0xffffffffu, bits, 4, 8);
        if (i2 < MM && e2 == 0) sBB[i2] = bits;
    }
    __syncthreads();
    // ---- symmetrize: C1 = B | B^T ----
    if (tid < MM) {
        unsigned mk = sBB[tid];
        #pragma unroll
        for (int jj = 0; jj < MM; jj++)
            mk |= ((sBB[jj] >> tid) & 1u) << jj;
        sMsk[tid] = mk;
    }

    // negated basec for own row: nb[t] = cM*(2*dot - f2n)  (packed)
    const int u = sNbr[r];
    u64 nb2[5];
    {
        const float2* drow = (const float2*)(g_D + (size_t)u * NKT + kk * MT);
        const float2* frow = (const float2*)(g_f2n + kk * MT);
        #pragma unroll
        for (int h = 0; h < 5; h++) {
            float2 v = __ldg(drow + h);
            float2 f = frow[h];
            nb2[h] = pk2(cM * (2.0f * v.x - f.x), cM * (2.0f * v.y - f.y));
        }
    }
    // row-0 negated basec element (s-lanes only)
    float nb0 = 0.f;
    if (sl) {
        float d0 = __ldg(g_D + (size_t)n * NKT + kk * MT + j);
        nb0 = cM * (2.0f * d0 - g_f2n[kk * MT + j]);
    }
    __syncthreads();   // masks ready

    // masks
    const unsigned mask = sMsk[r];
    const unsigned resmask = mask & ~1u;
    const int nres = __popc(resmask);
    const unsigned m0 = sMsk[0];
    const float c00 = (m0 & 1u) ? 0.f : -1.f;        // C1[0,0]-1

    // per-half colmask via shuffle-OR (each half ends with its own colmask)
    unsigned cmk = resmask;
    cmk |= __shfl_xor_sync(0xffffffffu, cmk, 1, 16);
    cmk |= __shfl_xor_sync(0xffffffffu, cmk, 2, 16);
    cmk |= __shfl_xor_sync(0xffffffffu, cmk, 4, 16);
    cmk |= __shfl_xor_sync(0xffffffffu, cmk, 8, 16);
    unsigned cmB = __shfl_sync(0xffffffffu, cmk, 16);
    __syncwarp();
    if (l == 0) {
        int L = 0;
        unsigned ca = cmk;
        while (ca) { int b = __ffs(ca)-1; ca &= ca-1; sList[w][L++] = b; }
        unsigned cb = cmB;
        while (cb) { int b = __ffs(cb)-1; cb &= cb-1; sList[w][L++] = 32 | b; }
        sLn[w] = L;
    }
    __syncwarp();
    const int L10 = 10 * sLn[w];
    int offA = 0, offB = 0, offW = 0;
    const bool hasTask = (l < L10);
    if (hasTask) {
        int p = l / 10, s2 = l - p*10;
        int ent = sList[w][p];
        int kt = w*2 + (ent >> 5); int b = ent & 31;
        offA = (kt*MT + s2) * MTP;
        offB = (kt*MM + b) * MTP;
        offW = offB + s2;
    }

    // persistent packed C2 row for s-lanes; rowsums for peel
    u64 cr2[5];
    {
        const float* crp = &sC2[kk][sl ? j : 0][0];
        ulonglong2 c01 = *(const ulonglong2*)crp;
        ulonglong2 c23 = *(const ulonglong2*)(crp + 4);
        cr2[0] = c01.x; cr2[1] = c01.y; cr2[2] = c23.x; cr2[3] = c23.y;
        cr2[4] = *(const u64*)(crp + 8);
    }
    float rsown, rs2own;
    {
        u64 rp = add2(add2(cr2[0], cr2[1]), add2(cr2[2], cr2[3]));
        rp = add2(rp, cr2[4]);
        rsown = hsum2(rp);
        u64 sp = mul2(cr2[0], cr2[0]);
        sp = fma2(cr2[1], cr2[1], sp);
        sp = fma2(cr2[2], cr2[2], sp);
        sp = fma2(cr2[3], cr2[3], sp);
        sp = fma2(cr2[4], cr2[4], sp);
        rs2own = hsum2(sp);
    }
    if (sl) { sRS[kk][j] = rsown; sRS2[kk][j] = rs2own; }
    __syncwarp();

    // ---- peeled iteration 0 (T uniform = 1/170), packed ----
    const float E0 = 1.0f / 170.0f;
    const float g2 = 0.1f * cA;
    u64 lt2[5];
    {
        float cf = cY * (E0 * (1.0f + (float)nres));
        u64 cf2 = pk2(cf, cf);
        u64 ng2 = pk2(-g2, -g2);
        const float* rsp  = &sRS [kk][0];
        const float* rs2p = &sRS2[kk][0];
        ulonglong2 ra = *(const ulonglong2*)rsp;
        ulonglong2 rb = *(const ulonglong2*)(rsp + 4);
        u64 rc = *(const u64*)(rsp + 8);
        ulonglong2 sa = *(const ulonglong2*)rs2p;
        ulonglong2 sb = *(const ulonglong2*)(rs2p + 4);
        u64 sc = *(const u64*)(rs2p + 8);
        lt2[0] = fma2(cf2, ra.x, fma2(ng2, sa.x, nb2[0]));
        lt2[1] = fma2(cf2, ra.y, fma2(ng2, sa.y, nb2[1]));
        lt2[2] = fma2(cf2, rb.x, fma2(ng2, sb.x, nb2[2]));
        lt2[3] = fma2(cf2, rb.y, fma2(ng2, sb.y, nb2[3]));
        lt2[4] = fma2(cf2, rc,   fma2(ng2, sc,   nb2[4]));
    }
    float lt0 = 0.f;
    if (sl) lt0 = cY * (0.1f + c00 * E0) * rsown - g2 * rs2own + nb0;

    float w0own = 0.f;

    #pragma unroll 1
    for (int it = 1; it <= 10; it++) {
        // phase 1: softmax own row + store; distributed row-0 softmax
        {
            float f[MT];
            up2(lt2[0], f[0], f[1]); up2(lt2[1], f[2], f[3]);
            up2(lt2[2], f[4], f[5]); up2(lt2[3], f[6], f[7]);
            up2(lt2[4], f[8], f[9]);
            float mx = f[0];
            #pragma unroll
            for (int t = 1; t < MT; t++) mx = fmaxf(mx, f[t]);
            float e[MT];
            #pragma unroll
            for (int t = 0; t < MT; t++) e[t] = __expf(f[t] - mx);
            u64 e2[5];
            #pragma unroll
            for (int h = 0; h < 5; h++) e2[h] = pk2(e[2*h], e[2*h+1]);
            u64 sp = add2(add2(e2[0], e2[1]), add2(e2[2], e2[3]));
            sp = add2(sp, e2[4]);
            float pr = (1.0f / MM) / hsum2(sp);
            u64 pr2 = pk2(pr, pr);
            #pragma unroll
            for (int h = 0; h < 5; h++) e2[h] = mul2(e2[h], pr2);
            float* Trow = &sT[kk][r][0];
            ulonglong2 st0; st0.x = e2[0]; st0.y = e2[1];
            ulonglong2 st1; st1.x = e2[2]; st1.y = e2[3];
            *(ulonglong2*)Trow = st0;
            *(ulonglong2*)(Trow + 4) = st1;
            *(u64*)(Trow + 8) = e2[4];
        }
        {
            float mx0 = sl ? lt0 : -3.0e38f;
            mx0 = fmaxf(mx0, __shfl_xor_sync(0xffffffffu, mx0, 1, 16));
            mx0 = fmaxf(mx0, __shfl_xor_sync(0xffffffffu, mx0, 2, 16));
            mx0 = fmaxf(mx0, __shfl_xor_sync(0xffffffffu, mx0, 4, 16));
            mx0 = fmaxf(mx0, __shfl_xor_sync(0xffffffffu, mx0, 8, 16));
            float e0 = sl ? __expf(lt0 - mx0) : 0.f;
            float s0 = e0;
            s0 += __shfl_xor_sync(0xffffffffu, s0, 1, 16);
            s0 += __shfl_xor_sync(0xffffffffu, s0, 2, 16);
            s0 += __shfl_xor_sync(0xffffffffu, s0, 4, 16);
            s0 += __shfl_xor_sync(0xffffffffu, s0, 8, 16);
            if (sl) sT[kk][0][j] = e0 * ((1.0f / MM) / s0);
        }
        __syncwarp();

        if (it == 10) break;   // final T stored; epilogue computes q

        // phase 2: colsum + W0 (s-lanes); worklist dots (all lanes)
        if (sl) {
            float qv = 0.f;
            #pragma unroll
            for (int b = 0; b < MM; b++) qv += sT[kk][b][j];
            sq[kk][j] = qv;

            const float* t0p = &sT[kk][0][0];
            ulonglong2 t01 = *(const ulonglong2*)t0p;
            ulonglong2 t23 = *(const ulonglong2*)(t0p + 4);
            u64 t4 = *(const u64*)(t0p + 8);
            u64 wp = mul2(cr2[0], t01.x);
            wp = fma2(cr2[1], t01.y, wp);
            wp = fma2(cr2[2], t23.x, wp);
            wp = fma2(cr2[3], t23.y, wp);
            wp = fma2(cr2[4], t4,   wp);
            w0own = hsum2(wp);
        }
        if (hasTask)
            ((float*)sW)[offW] = cY * dot10p(&((const float*)sC2)[offA],
                                            &((const float*)sT)[offB]);
        for (int idx = l + 32; idx < L10; idx += 32) {
            int p = idx / 10, s2 = idx - p*10;
            int ent = sList[w][p];
            int kt = w*2 + (ent >> 5); int b = ent & 31;
            sW[kt][b][s2] = cY * dot10p(&sC2[kt][s2][0], &sT[kt][b][0]);
        }
        __syncwarp();

        // phase 3: s-lanes: packed Zq/cc; publish U; update row-0 logit
        if (sl) {
            const float* qp = &sq[kk][0];
            ulonglong2 q01 = *(const ulonglong2*)qp;
            ulonglong2 q23 = *(const ulonglong2*)(qp + 4);
            u64 q4 = *(const u64*)(qp + 8);
            u64 t0 = mul2(cr2[0], q01.x);
            u64 t1 = mul2(cr2[1], q01.y);
            u64 t2 = mul2(cr2[2], q23.x);
            u64 t3 = mul2(cr2[3], q23.y);
            u64 t4 = mul2(cr2[4], q4);
            u64 zp = add2(add2(t0, t1), add2(t2, t3));
            zp = add2(zp, t4);
            u64 cp = mul2(t0, cr2[0]);
            cp = fma2(t1, cr2[1], cp);
            cp = fma2(t2, cr2[2], cp);
            cp = fma2(t3, cr2[3], cp);
            cp = fma2(t4, cr2[4], cp);
            float zq = hsum2(zp);
            float gcs = cA * hsum2(cp);
            sU[kk][j] = cY * w0own - gcs;
            lt0 += cY * fmaf(c00, w0own, zq) - gcs + nb0;
        }
        __syncwarp();

        // phase 4: all lanes packed update: lt += U + nb (+ residual rows)
        {
            const float* Ur = &sU[kk][0];
            ulonglong2 u01 = *(const ulonglong2*)Ur;
            ulonglong2 u23 = *(const ulonglong2*)(Ur + 4);
            u64 u4 = *(const u64*)(Ur + 8);
            lt2[0] = add2(lt2[0], add2(u01.x, nb2[0]));
            lt2[1] = add2(lt2[1], add2(u01.y, nb2[1]));
            lt2[2] = add2(lt2[2], add2(u23.x, nb2[2]));
            lt2[3] = add2(lt2[3], add2(u23.y, nb2[3]));
            lt2[4] = add2(lt2[4], add2(u4,    nb2[4]));

            unsigned rm = resmask;
            while (rm) {
                int b = __ffs(rm) - 1; rm &= rm - 1;
                const float* Wr = &sW[kk][b][0];
                ulonglong2 w01 = *(const ulonglong2*)Wr;
                ulonglong2 w23 = *(const ulonglong2*)(Wr + 4);
                u64 w4 = *(const u64*)(Wr + 8);
                lt2[0] = add2(lt2[0], w01.x);
                lt2[1] = add2(lt2[1], w01.y);
                lt2[2] = add2(lt2[2], w23.x);
                lt2[3] = add2(lt2[3], w23.y);
                lt2[4] = add2(lt2[4], w4);
            }
        }
    }

    // epilogue: final marginal q (T already stored at it==10)
    if (sl) {
        float qv = 0.f;
        #pragma unroll
        for (int b = 0; b < MM; b++) qv += sT[kk][b][j];
        out[(size_t)n * NKT + kk * MT + j] = qv;
    }
}

// ---------------- launch ----------------
extern "C" void kernel_launch(void* const* d_in, const int* in_sizes, int n_in,
                              void* d_out, int out_size) {
    const float* x      = (const float*)d_in[0];
    const int*   eidx   = (const int*)d_in[1];
    const float* C2g    = (const float*)d_in[2];
    const float* F2     = (const float*)d_in[3];
    const float* alpha0 = (const float*)d_in[4];
    float* out = (float*)d_out;

    const int* dst = eidx + NN * DEG;   // row 1 of edge_index

    k_prep<<<PREP_BLOCKS, 272>>>(x, F2, alpha0);
    k_main<<<NN, TPB_MAIN>>>(C2g, dst, out);
}

// round 17
// speedup vs baseline: 1.0585x; 1.0585x over previous
#include <cuda_runtime.h>
#include <cuda_bf16.h>

#define NN    6000
#define DEG   16
#define MM    17      // DEG+1
#define NT    16
#define MT    10
#define MTP   12      // padded row (floats)
#define NF    128
#define NKT   (NT*MT) // 160
#define REGc  0.1f
#define NWARPS 2
#define NTPB  4                        // templates per main block
#define TPB_MAIN 64

#define GEMM_BLOCKS   ((NN + 31) / 32)          // 188 (32 rows per block)
#define SETUP_BLOCK   GEMM_BLOCKS               // 188
#define ADJ_BLOCK0    (GEMM_BLOCKS + 1)         // 189
#define NPB           16
#define ADJ_BLOCKS    ((NN + NPB - 1) / NPB)    // 375
#define PREP_BLOCKS   (ADJ_BLOCK0 + ADJ_BLOCKS) // 564

typedef unsigned long long u64;

// ---------------- device scratch (no cudaMalloc allowed) ----------------
__device__ int      g_nbrs[NN * MM];
__device__ unsigned g_mask[NN * MM];
__device__ float    g_f2n[NKT];
__device__ float    g_consts[3];     // cA = 2a/REG, cY = 4a/REG, cM = (1-a)/REG
__device__ float    g_D[NN * NKT];   // raw dot:  x[u] . F2[kt]

// ---------------- packed f32x2 helpers ----------------
__device__ __forceinline__ u64 pk2(float x, float y) {
    u64 r; asm("mov.b64 %0,{%1,%2};" : "=l"(r) : "f"(x), "f"(y)); return r;
}
__device__ __forceinline__ void up2(u64 v, float& x, float& y) {
    asm("mov.b64 {%0,%1},%2;" : "=f"(x), "=f"(y) : "l"(v));
}
__device__ __forceinline__ u64 add2(u64 a, u64 b) {
    u64 r; asm("add.rn.f32x2 %0,%1,%2;" : "=l"(r) : "l"(a), "l"(b)); return r;
}
__device__ __forceinline__ u64 mul2(u64 a, u64 b) {
    u64 r; asm("mul.rn.f32x2 %0,%1,%2;" : "=l"(r) : "l"(a), "l"(b)); return r;
}
__device__ __forceinline__ u64 fma2(u64 a, u64 b, u64 c) {
    u64 r; asm("fma.rn.f32x2 %0,%1,%2,%3;" : "=l"(r) : "l"(a), "l"(b), "l"(c)); return r;
}
__device__ __forceinline__ float hsum2(u64 v) {
    float x, y; up2(v, x, y); return x + y;
}

// packed f32x2 dot over 10 elements (both operands 16B-aligned smem rows)
__device__ __forceinline__ float dot10p(const float* __restrict__ a,
                                        const float* __restrict__ b) {
    const ulonglong2* A = (const ulonglong2*)a;
    const ulonglong2* B = (const ulonglong2*)b;
    ulonglong2 A0 = A[0], A1 = A[1];
    ulonglong2 B0 = B[0], B1 = B[1];
    u64 a2 = *(const u64*)(a + 8);
    u64 b2 = *(const u64*)(b + 8);
    u64 acc = mul2(A0.x, B0.x);
    acc = fma2(A0.y, B0.y, acc);
    acc = fma2(A1.x, B1.x, acc);
    acc = fma2(A1.y, B1.y, acc);
    acc = fma2(a2,   b2,   acc);
    return hsum2(acc);
}

// ---------------- fused prologue: setup | gemm | adjacency ----------------
__global__ void __launch_bounds__(272, 3)
k_prep(const float* __restrict__ x, const float* __restrict__ F2,
       const float* __restrict__ alpha0, const int* __restrict__ dst) {
    __shared__ float sX[32][33];
    __shared__ float sF[32][161];
    __shared__ unsigned sB[NPB][MM];

    const int tid = threadIdx.x;
    const int blk = blockIdx.x;

    if (blk < GEMM_BLOCKS) {
        const int tr = tid & 15;
        const int tc = (tid >> 4) & 15;
        const bool act = (tid < 256);
        const int r0 = blk * 32;

        float acc[2][10];
        #pragma unroll
        for (int i = 0; i < 2; i++)
            #pragma unroll
            for (int j = 0; j < 10; j++) acc[i][j] = 0.f;

        for (int k0 = 0; k0 < NF; k0 += 32) {
            __syncthreads();
            for (int idx = tid; idx < 256; idx += 272) {
                int rr = idx >> 3, c4 = idx & 7;
                int gr = r0 + rr;
                float4 v = (gr < NN) ? __ldg((const float4*)(x + (size_t)gr * NF + k0) + c4)
                                     : make_float4(0.f, 0.f, 0.f, 0.f);
                sX[c4*4+0][rr] = v.x; sX[c4*4+1][rr] = v.y;
                sX[c4*4+2][rr] = v.z; sX[c4*4+3][rr] = v.w;
            }
            for (int idx = tid; idx < 1280; idx += 272) {
                int cc = idx >> 3, c4 = idx & 7;
                float4 v = __ldg((const float4*)(F2 + (size_t)cc * NF + k0) + c4);
                sF[c4*4+0][cc] = v.x; sF[c4*4+1][cc] = v.y;
                sF[c4*4+2][cc] = v.z; sF[c4*4+3][cc] = v.w;
            }
            __syncthreads();

            if (act) {
                #pragma unroll 4
                for (int kk = 0; kk < 32; kk++) {
                    float b[10];
                    #pragma unroll
                    for (int j = 0; j < 10; j++) b[j] = sF[kk][tc*10 + j];
                    #pragma unroll
                    for (int i = 0; i < 2; i++) {
                        float a = sX[kk][tr + 16*i];
                        #pragma unroll
                        for (int j = 0; j < 10; j++) acc[i][j] = fmaf(a, b[j], acc[i][j]);
                    }
                }
            }
        }

        if (act) {
            #pragma unroll
            for (int i = 0; i < 2; i++) {
                int r = r0 + tr + 16*i;
                if (r < NN) {
                    float* drow = g_D + (size_t)r * NKT + tc*10;
                    #pragma unroll
                    for (int j = 0; j < 10; j++) drow[j] = acc[i][j];
                }
            }
        }
    } else if (blk == SETUP_BLOCK) {
        if (tid == 0) {
            float a0 = alpha0[0];
            float alpha = 1.0f / (1.0f + __expf(-a0));
            g_consts[0] = 2.0f * alpha / REGc;
            g_consts[1] = 4.0f * alpha / REGc;
            g_consts[2] = (1.0f - alpha) / REGc;
        }
        for (int idx = tid; idx < NKT; idx += 272) {
            const float* row = F2 + (size_t)idx * NF;
            float s = 0.f;
            #pragma unroll 8
            for (int f = 0; f < NF; f++) { float v = row[f]; s += v * v; }
            g_f2n[idx] = s;
        }
    } else {
        const int ln = tid / MM;
        const int i  = tid - ln * MM;
        const int n  = (blk - ADJ_BLOCK0) * NPB + ln;
        const bool ok = (n < NN) && (ln < NPB);

        if (ok) {
            const int* dstn = dst + (size_t)n * DEG;
            int u = (i == 0) ? n : dstn[i - 1];
            g_nbrs[n * MM + i] = u;

            const int* dstu = dst + (size_t)u * DEG;
            int du[DEG];
            #pragma unroll
            for (int e = 0; e < DEG; e++) du[e] = dstu[e];
            int dn[DEG];
            #pragma unroll
            for (int e = 0; e < DEG; e++) dn[e] = dstn[e];

            unsigned bits = 0;
            #pragma unroll
            for (int j = 0; j < MM; j++) {
                int v = (j == 0) ? n : dn[j - 1];
                bool hit = false;
                #pragma unroll
                for (int e = 0; e < DEG; e++) hit |= (du[e] == v);
                bits |= (unsigned)hit << j;
            }
            sB[ln][i] = bits;
        }
        __syncthreads();
        if (ok) {
            unsigned mk = sB[ln][i];
            #pragma unroll
            for (int j = 0; j < MM; j++)
                mk |= ((sB[ln][j] >> i) & 1u) << j;
            g_mask[n * MM + i] = mk;
        }
    }
}

// ---------------- main: warp-synchronous, 64-thread blocks ----------------
// block = 4 templates of one node (2 warps); blockIdx = n*4 + quarter
// warp = 2 templates x 16 rows (+ distributed row 0)
__global__ void __launch_bounds__(TPB_MAIN, 12)
k_main(const float* __restrict__ C2g, float* __restrict__ out) {
    __shared__ __align__(16) float sT [NTPB][MM][MTP];
    __shared__ __align__(16) float sW [NTPB][MM][MTP];
    __shared__ __align__(16) float sC2[NTPB][MT][MTP];
    __shared__ __align__(16) float sq [NTPB][MTP];
    __shared__ __align__(16) float sU [NTPB][MTP];
    __shared__ __align__(16) float sRS [NTPB][MTP];
    __shared__ __align__(16) float sRS2[NTPB][MTP];
    __shared__ int sList[NWARPS][32];
    __shared__ int sLn[NWARPS];

    const int tid = threadIdx.x;
    const int bid = blockIdx.x;
    const int n   = bid >> 2;
    const int kh  = (bid & 3) * NTPB;  // template base 0,4,8,12
    const int w   = tid >> 5;          // 0..1
    const int l   = tid & 31;
    const int g   = l >> 4;            // template within warp
    const int j   = l & 15;            // 0..15
    const int kk  = w * 2 + g;         // local template 0..3
    const int kkg = kh + kk;           // global template 0..15
    const int r   = j + 1;             // own row 1..16
    const bool sl = (j < MT);          // s-lane (owns output column j)

    const float cA = g_consts[0];
    const float cY = g_consts[1];
    const float cM = g_consts[2];

    // warp-local C2 load (2 templates)
    for (int idx = l; idx < 2 * MT * MTP; idx += 32) {
        int kl = w*2 + idx / (MT*MTP);
        int rr  = idx % (MT*MTP);
        int s2  = rr / MTP, t2 = rr % MTP;
        sC2[kl][s2][t2] = (t2 < MT) ? C2g[((kh + kl)*MT + s2)*MT + t2] : 0.f;
    }

    // negated basec for own row: nb[t] = cM*(2*dot - f2n)  (packed)
    const int u = g_nbrs[n*MM + r];
    u64 nb2[5];
    {
        const float2* drow = (const float2*)(g_D + (size_t)u * NKT + kkg * MT);
        const float2* frow = (const float2*)(g_f2n + kkg * MT);
        #pragma unroll
        for (int h = 0; h < 5; h++) {
            float2 v = __ldg(drow + h);
            float2 f = frow[h];
            nb2[h] = pk2(cM * (2.0f * v.x - f.x), cM * (2.0f * v.y - f.y));
        }
    }
    // row-0 negated basec element (s-lanes only)
    float nb0 = 0.f;
    if (sl) {
        float d0 = __ldg(g_D + (size_t)n * NKT + kkg * MT + j);
        nb0 = cM * (2.0f * d0 - g_f2n[kkg * MT + j]);
    }

    // masks
    const unsigned mask = g_mask[n*MM + r];
    const unsigned resmask = mask & ~1u;
    const int nres = __popc(resmask);
    unsigned m0 = 0;
    if (j == 0) m0 = g_mask[n*MM];
    m0 = __shfl_sync(0xffffffffu, m0, 0, 16);
    const float c00 = (m0 & 1u) ? 0.f : -1.f;        // C1[0,0]-1

    // per-half colmask via shuffle-OR
    unsigned cmk = resmask;
    cmk |= __shfl_xor_sync(0xffffffffu, cmk, 1, 16);
    cmk |= __shfl_xor_sync(0xffffffffu, cmk, 2, 16);
    cmk |= __shfl_xor_sync(0xffffffffu, cmk, 4, 16);
    cmk |= __shfl_xor_sync(0xffffffffu, cmk, 8, 16);
    unsigned cmB = __shfl_sync(0xffffffffu, cmk, 16);
    __syncwarp();
    if (l == 0) {
        int L = 0;
        unsigned ca = cmk;
        while (ca) { int b = __ffs(ca)-1; ca &= ca-1; sList[w][L++] = b; }
        unsigned cb = cmB;
        while (cb) { int b = __ffs(cb)-1; cb &= cb-1; sList[w][L++] = 32 | b; }
        sLn[w] = L;
    }
    __syncwarp();
    const int L10 = 10 * sLn[w];
    int offA = 0, offB = 0, offW = 0;
    const bool hasTask = (l < L10);
    if (hasTask) {
        int p = l / 10, s2 = l - p*10;
        int ent = sList[w][p];
        int kt = w*2 + (ent >> 5); int b = ent & 31;
        offA = (kt*MT + s2) * MTP;
        offB = (kt*MM + b) * MTP;
        offW = offB + s2;
    }

    // persistent packed C2 row for s-lanes; rowsums for peel
    u64 cr2[5];
    {
        const float* crp = &sC2[kk][sl ? j : 0][0];
        ulonglong2 c01 = *(const ulonglong2*)crp;
        ulonglong2 c23 = *(const ulonglong2*)(crp + 4);
        cr2[0] = c01.x; cr2[1] = c01.y; cr2[2] = c23.x; cr2[3] = c23.y;
        cr2[4] = *(const u64*)(crp + 8);
    }
    float rsown, rs2own;
    {
        u64 rp = add2(add2(cr2[0], cr2[1]), add2(cr2[2], cr2[3]));
        rp = add2(rp, cr2[4]);
        rsown = hsum2(rp);
        u64 sp = mul2(cr2[0], cr2[0]);
        sp = fma2(cr2[1], cr2[1], sp);
        sp = fma2(cr2[2], cr2[2], sp);
        sp = fma2(cr2[3], cr2[3], sp);
        sp = fma2(cr2[4], cr2[4], sp);
        rs2own = hsum2(sp);
    }
    if (sl) { sRS[kk][j] = rsown; sRS2[kk][j] = rs2own; }
    __syncwarp();

    // ---- peeled iteration 0 (T uniform = 1/170), packed ----
    const float E0 = 1.0f / 170.0f;
    const float g2 = 0.1f * cA;
    u64 lt2[5];
    {
        float cf = cY * (E0 * (1.0f + (float)nres));
        u64 cf2 = pk2(cf, cf);
        u64 ng2 = pk2(-g2, -g2);
        const float* rsp  = &sRS [kk][0];
        const float* rs2p = &sRS2[kk][0];
        ulonglong2 ra = *(const ulonglong2*)rsp;
        ulonglong2 rb = *(const ulonglong2*)(rsp + 4);
        u64 rc = *(const u64*)(rsp + 8);
        ulonglong2 sa = *(const ulonglong2*)rs2p;
        ulonglong2 sb = *(const ulonglong2*)(rs2p + 4);
        u64 sc = *(const u64*)(rs2p + 8);
        lt2[0] = fma2(cf2, ra.x, fma2(ng2, sa.x, nb2[0]));
        lt2[1] = fma2(cf2, ra.y, fma2(ng2, sa.y, nb2[1]));
        lt2[2] = fma2(cf2, rb.x, fma2(ng2, sb.x, nb2[2]));
        lt2[3] = fma2(cf2, rb.y, fma2(ng2, sb.y, nb2[3]));
        lt2[4] = fma2(cf2, rc,   fma2(ng2, sc,   nb2[4]));
    }
    float lt0 = 0.f;
    if (sl) lt0 = cY * (0.1f + c00 * E0) * rsown - g2 * rs2own + nb0;

    float w0own = 0.f;

    #pragma unroll 1
    for (int it = 1; it <= 10; it++) {
        // phase 1: softmax own row + store; distributed row-0 softmax
        {
            float f[MT];
            up2(lt2[0], f[0], f[1]); up2(lt2[1], f[2], f[3]);
            up2(lt2[2], f[4], f[5]); up2(lt2[3], f[6], f[7]);
            up2(lt2[4], f[8], f[9]);
            float mx = f[0];
            #pragma unroll
            for (int t = 1; t < MT; t++) mx = fmaxf(mx, f[t]);
            float e[MT];
            #pragma unroll
            for (int t = 0; t < MT; t++) e[t] = __expf(f[t] - mx);
            u64 e2[5];
            #pragma unroll
            for (int h = 0; h < 5; h++) e2[h] = pk2(e[2*h], e[2*h+1]);
            u64 sp = add2(add2(e2[0], e2[1]), add2(e2[2], e2[3]));
            sp = add2(sp, e2[4]);
            float pr = (1.0f / MM) / hsum2(sp);
            u64 pr2 = pk2(pr, pr);
            #pragma unroll
            for (int h = 0; h < 5; h++) e2[h] = mul2(e2[h], pr2);
            float* Trow = &sT[kk][r][0];
            ulonglong2 st0; st0.x = e2[0]; st0.y = e2[1];
            ulonglong2 st1; st1.x = e2[2]; st1.y = e2[3];
            *(ulonglong2*)Trow = st0;
            *(ulonglong2*)(Trow + 4) = st1;
            *(u64*)(Trow + 8) = e2[4];
        }
        {
            float mx0 = sl ? lt0 : -3.0e38f;
            mx0 = fmaxf(mx0, __shfl_xor_sync(0xffffffffu, mx0, 1, 16));
            mx0 = fmaxf(mx0, __shfl_xor_sync(0xffffffffu, mx0, 2, 16));
            mx0 = fmaxf(mx0, __shfl_xor_sync(0xffffffffu, mx0, 4, 16));
            mx0 = fmaxf(mx0, __shfl_xor_sync(0xffffffffu, mx0, 8, 16));
            float e0 = sl ? __expf(lt0 - mx0) : 0.f;
            float s0 = e0;
            s0 += __shfl_xor_sync(0xffffffffu, s0, 1, 16);
            s0 += __shfl_xor_sync(0xffffffffu, s0, 2, 16);
            s0 += __shfl_xor_sync(0xffffffffu, s0, 4, 16);
            s0 += __shfl_xor_sync(0xffffffffu, s0, 8, 16);
            if (sl) sT[kk][0][j] = e0 * ((1.0f / MM) / s0);
        }
        __syncwarp();

        if (it == 10) break;   // final T stored; epilogue computes q

        // phase 2: colsum + W0 (s-lanes); worklist dots (all lanes)
        if (sl) {
            float qv = 0.f;
            #pragma unroll
            for (int b = 0; b < MM; b++) qv += sT[kk][b][j];
            sq[kk][j] = qv;

            const float* t0p = &sT[kk][0][0];
            ulonglong2 t01 = *(const ulonglong2*)t0p;
            ulonglong2 t23 = *(const ulonglong2*)(t0p + 4);
            u64 t4 = *(const u64*)(t0p + 8);
            u64 wp = mul2(cr2[0], t01.x);
            wp = fma2(cr2[1], t01.y, wp);
            wp = fma2(cr2[2], t23.x, wp);
            wp = fma2(cr2[3], t23.y, wp);
            wp = fma2(cr2[4], t4,   wp);
            w0own = hsum2(wp);
        }
        if (hasTask)
            ((float*)sW)[offW] = cY * dot10p(&((const float*)sC2)[offA],
                                            &((const float*)sT)[offB]);
        for (int idx = l + 32; idx < L10; idx += 32) {
            int p = idx / 10, s2 = idx - p*10;
            int ent = sList[w][p];
            int kt = w*2 + (ent >> 5); int b = ent & 31;
            sW[kt][b][s2] = cY * dot10p(&sC2[kt][s2][0], &sT[kt][b][0]);
        }
        __syncwarp();

        // phase 3: s-lanes: packed Zq/cc; publish U; update row-0 logit
        if (sl) {
            const float* qp = &sq[kk][0];
            ulonglong2 q01 = *(const ulonglong2*)qp;
            ulonglong2 q23 = *(const ulonglong2*)(qp + 4);
            u64 q4 = *(const u64*)(qp + 8);
            u64 t0 = mul2(cr2[0], q01.x);
            u64 t1 = mul2(cr2[1], q01.y);
            u64 t2 = mul2(cr2[2], q23.x);
            u64 t3 = mul2(cr2[3], q23.y);
            u64 t4 = mul2(cr2[4], q4);
            u64 zp = add2(add2(t0, t1), add2(t2, t3));
            zp = add2(zp, t4);
            u64 cp = mul2(t0, cr2[0]);
            cp = fma2(t1, cr2[1], cp);
            cp = fma2(t2, cr2[2], cp);
            cp = fma2(t3, cr2[3], cp);
            cp = fma2(t4, cr2[4], cp);
            float zq = hsum2(zp);
            float gcs = cA * hsum2(cp);
            sU[kk][j] = cY * w0own - gcs;
            lt0 += cY * fmaf(c00, w0own, zq) - gcs + nb0;
        }
        __syncwarp();

        // phase 4: all lanes packed update: lt += U + nb (+ residual rows)
        {
            const float* Ur = &sU[kk][0];
            ulonglong2 u01 = *(const ulonglong2*)Ur;
            ulonglong2 u23 = *(const ulonglong2*)(Ur + 4);
            u64 u4 = *(const u64*)(Ur + 8);
            lt2[0] = add2(lt2[0], add2(u01.x, nb2[0]));
            lt2[1] = add2(lt2[1], add2(u01.y, nb2[1]));
            lt2[2] = add2(lt2[2], add2(u23.x, nb2[2]));
            lt2[3] = add2(lt2[3], add2(u23.y, nb2[3]));
            lt2[4] = add2(lt2[4], add2(u4,    nb2[4]));

            unsigned rm = resmask;
            while (rm) {
                int b = __ffs(rm) - 1; rm &= rm - 1;
                const float* Wr = &sW[kk][b][0];
                ulonglong2 w01 = *(const ulonglong2*)Wr;
                ulonglong2 w23 = *(const ulonglong2*)(Wr + 4);
                u64 w4 = *(const u64*)(Wr + 8);
                lt2[0] = add2(lt2[0], w01.x);
                lt2[1] = add2(lt2[1], w01.y);
                lt2[2] = add2(lt2[2], w23.x);
                lt2[3] = add2(lt2[3], w23.y);
                lt2[4] = add2(lt2[4], w4);
            }
        }
    }

    // epilogue: final marginal q (T already stored at it==10)
    if (sl) {
        float qv = 0.f;
        #pragma unroll
        for (int b = 0; b < MM; b++) qv += sT[kk][b][j];
        out[(size_t)n * NKT + kkg * MT + j] = qv;
    }
}

// ---------------- launch ----------------
extern "C" void kernel_launch(void* const* d_in, const int* in_sizes, int n_in,
                              void* d_out, int out_size) {
    const float* x      = (const float*)d_in[0];
    const int*   eidx   = (const int*)d_in[1];
    const float* C2g    = (const float*)d_in[2];
    const float* F2     = (const float*)d_in[3];
    const float* alpha0 = (const float*)d_in[4];
    float* out = (float*)d_out;

    const int* dst = eidx + NN * DEG;   // row 1 of edge_index

    k_prep<<<PREP_BLOCKS, 272>>>(x, F2, alpha0, dst);
    k_main<<<NN * 4, TPB_MAIN>>>(C2g, out);
}